// round 14
// baseline (speedup 1.0000x reference)
#include <cuda_runtime.h>
#include <cuda_fp16.h>
#include <math.h>
#include <stdint.h>

#define NN 50000
#define EE 800000
#define HID 512
#define HC 256
#define NCLS 40
#define QS 1024     // interleaved qkv+skip stride (halfs)
#define NBLK 196    // ceil(NN/256)

// weight-buffer offsets (fp16-converted, row-major [N][K])
#define OFF_QKVS 0
#define OFF_W1   262144
#define OFF_W2   393216
#define OFF_W3   655360
#define OFF_WC1  786432
#define OFF_WC2  917504
#define WTF_TOT  937984

// ---------------- scratch ----------------------------------------------------
__device__ __half g_qkvs[(size_t)NN * QS];  // q[0,256) k[256,512) v[512,768) hg[768,1024)
__device__ __half g_h1[(size_t)NN * HID];
__device__ __half g_h2[(size_t)NN * HID];
__device__ __half g_xg[(size_t)NN * 256];   // fp16 copy of x_gsage
__device__ __half g_xm[(size_t)NN * 256];   // fp16 copy of x_mlp
__device__ int    g_deg[NN];
__device__ int    g_off[NN + 1];
__device__ int    g_cursor[NN];
__device__ int    g_csr_src[EE];
__device__ int    g_bsum[256];
__device__ int    g_bpref[256];
__device__ float  g_stats1[HID * 2];        // interleaved sum, sumsq
__device__ float  g_stats2[HID * 2];
__device__ float  g_mu1[HID], g_rsig1[HID], g_mu2[HID], g_rsig2[HID];
__device__ __half g_wh[WTF_TOT];
__device__ float  g_bcat[QS];

// ---------------- helpers ----------------------------------------------------
__device__ __forceinline__ void redAdd4(float* p, float a, float b, float c, float d) {
    asm volatile("red.global.add.v4.f32 [%0], {%1,%2,%3,%4};"
                 :: "l"(p), "f"(a), "f"(b), "f"(c), "f"(d) : "memory");
}
__device__ __forceinline__ float4 ld4h(const __half* p) {
    uint2 u = *(const uint2*)p;
    __half2 h0 = *(__half2*)&u.x, h1 = *(__half2*)&u.y;
    float2 a = __half22float2(h0), b = __half22float2(h1);
    return make_float4(a.x, a.y, b.x, b.y);
}
__device__ __forceinline__ void st4h(__half* p, float4 v) {
    uint2 u;
    __half2 h0 = __float22half2_rn(make_float2(v.x, v.y));
    __half2 h1 = __float22half2_rn(make_float2(v.z, v.w));
    u.x = *(unsigned*)&h0; u.y = *(unsigned*)&h1;
    *(uint2*)p = u;
}
__device__ __forceinline__ void cvt8(float* f, uint4 u) {
    __half2* h = (__half2*)&u;
#pragma unroll
    for (int i = 0; i < 4; i++) {
        float2 t = __half22float2(h[i]);
        f[2 * i] = t.x; f[2 * i + 1] = t.y;
    }
}
__device__ __forceinline__ void ldsm4(unsigned& r0, unsigned& r1, unsigned& r2, unsigned& r3,
                                      unsigned addr) {
    asm volatile("ldmatrix.sync.aligned.m8n8.x4.shared.b16 {%0,%1,%2,%3}, [%4];"
                 : "=r"(r0), "=r"(r1), "=r"(r2), "=r"(r3) : "r"(addr));
}
__device__ __forceinline__ void mma16(float* d, const unsigned* a, const unsigned* b) {
    asm volatile("mma.sync.aligned.m16n8k16.row.col.f32.f16.f16.f32 "
                 "{%0,%1,%2,%3},{%4,%5,%6,%7},{%8,%9},{%0,%1,%2,%3};"
                 : "+f"(d[0]), "+f"(d[1]), "+f"(d[2]), "+f"(d[3])
                 : "r"(a[0]), "r"(a[1]), "r"(a[2]), "r"(a[3]), "r"(b[0]), "r"(b[1]));
}

// ---------------- preconvert weights to fp16 + concat biases -----------------
__global__ void preconv(const float* __restrict__ Wq, const float* __restrict__ Wk,
                        const float* __restrict__ Wv, const float* __restrict__ Ws,
                        const float* __restrict__ W1, const float* __restrict__ W2,
                        const float* __restrict__ W3, const float* __restrict__ Wc1,
                        const float* __restrict__ Wc2,
                        const float* __restrict__ bq, const float* __restrict__ bk,
                        const float* __restrict__ bv, const float* __restrict__ bs)
{
    int i = blockIdx.x * 256 + threadIdx.x;
    if (i < WTF_TOT) {
        float v;
        if (i < OFF_W1) {
            int wsel = i >> 16, idx = i & 65535;
            const float* src = (wsel == 0) ? Wq : (wsel == 1) ? Wk : (wsel == 2) ? Wv : Ws;
            v = src[idx];
        } else if (i < OFF_W2)  v = W1[i - OFF_W1];
        else if (i < OFF_W3)    v = W2[i - OFF_W2];
        else if (i < OFF_WC1)   v = W3[i - OFF_W3];
        else if (i < OFF_WC2)   v = Wc1[i - OFF_WC1];
        else                    v = Wc2[i - OFF_WC2];
        g_wh[i] = __float2half_rn(v);
    } else if (i < WTF_TOT + QS) {
        int j = i - WTF_TOT;
        int sel = j >> 8, idx = j & 255;
        const float* src = (sel == 0) ? bq : (sel == 1) ? bk : (sel == 2) ? bv : bs;
        g_bcat[j] = src[idx];
    }
}

// fp32 -> fp16 bulk convert (8 elems/thread)
__global__ void __launch_bounds__(256)
cvt_f2h(const float* __restrict__ X, __half* __restrict__ Y, int n)
{
    int i = (blockIdx.x * 256 + threadIdx.x) * 8;
    if (i >= n) return;
    float4 a = *(const float4*)(X + i);
    float4 b = *(const float4*)(X + i + 4);
    uint4 u;
    __half2 h;
    h = __float22half2_rn(make_float2(a.x, a.y)); u.x = *(unsigned*)&h;
    h = __float22half2_rn(make_float2(a.z, a.w)); u.y = *(unsigned*)&h;
    h = __float22half2_rn(make_float2(b.x, b.y)); u.z = *(unsigned*)&h;
    h = __float22half2_rn(make_float2(b.z, b.w)); u.w = *(unsigned*)&h;
    *(uint4*)(Y + i) = u;
}

__global__ void init_stats() {
    int i = blockIdx.x * blockDim.x + threadIdx.x;
    if (i < HID * 2) {
        g_stats1[i] = 0.f;
        g_stats2[i] = 0.f;
    }
}

// ---------------- CSR build (parallel scan) -------------------------------------
__global__ void zero_deg() {
    int i = blockIdx.x * blockDim.x + threadIdx.x;
    if (i < NN) g_deg[i] = 0;
}
__global__ void count_deg(const int* __restrict__ ei) {
    int e = blockIdx.x * blockDim.x + threadIdx.x;
    if (e >= EE) return;
    atomicAdd(&g_deg[ei[EE + e]], 1);
}
__global__ void __launch_bounds__(256)
deg_block_sums() {
    int i = blockIdx.x * 256 + threadIdx.x;
    int v = (i < NN) ? g_deg[i] : 0;
#pragma unroll
    for (int o = 16; o; o >>= 1) v += __shfl_xor_sync(0xFFFFFFFFu, v, o);
    __shared__ int ws[8];
    if ((threadIdx.x & 31) == 0) ws[threadIdx.x >> 5] = v;
    __syncthreads();
    if (threadIdx.x < 8) {
        int s = ws[threadIdx.x];
#pragma unroll
        for (int o = 4; o; o >>= 1) s += __shfl_xor_sync(0xFFu, s, o);
        if (threadIdx.x == 0) g_bsum[blockIdx.x] = s;
    }
}
__global__ void __launch_bounds__(256)
scan_bsums() {
    __shared__ int sm[256];
    int t = threadIdx.x;
    int v = (t < NBLK) ? g_bsum[t] : 0;
    sm[t] = v;
    __syncthreads();
#pragma unroll
    for (int s = 1; s < 256; s <<= 1) {
        int u = (t >= s) ? sm[t - s] : 0;
        __syncthreads();
        sm[t] += u;
        __syncthreads();
    }
    if (t < NBLK) g_bpref[t] = sm[t] - v;
}
__global__ void __launch_bounds__(256)
write_offsets() {
    __shared__ int sm[256];
    int t = threadIdx.x;
    int i = blockIdx.x * 256 + t;
    int v = (i < NN) ? g_deg[i] : 0;
    sm[t] = v;
    __syncthreads();
#pragma unroll
    for (int s = 1; s < 256; s <<= 1) {
        int u = (t >= s) ? sm[t - s] : 0;
        __syncthreads();
        sm[t] += u;
        __syncthreads();
    }
    if (i < NN) {
        int off = g_bpref[blockIdx.x] + sm[t];
        g_off[i + 1] = off;
        g_cursor[i] = off - v;
    }
    if (i == 0) g_off[0] = 0;
}
__global__ void scatter_edges(const int* __restrict__ ei) {
    int e = blockIdx.x * blockDim.x + threadIdx.x;
    if (e >= EE) return;
    int src = ei[e];
    int dst = ei[EE + e];
    int pos = atomicAdd(&g_cursor[dst], 1);
    g_csr_src[pos] = src;
}

// ---------------- fused attention: warp per node, unroll-2 online softmax ------
__global__ void __launch_bounds__(256)
attn_fused()
{
    int nid = blockIdx.x * 8 + (threadIdx.x >> 5);
    if (nid >= NN) return;
    int lane = threadIdx.x & 31;
    int head = lane >> 4;
    int c = (lane & 15) * 8;

    const size_t row = (size_t)nid * QS;
    float q[8];
    cvt8(q, *(const uint4*)(g_qkvs + row + head * 128 + c));
#pragma unroll
    for (int i = 0; i < 8; i++) q[i] *= 0.08838834764831845f;

    int beg = g_off[nid], end = g_off[nid + 1];
    if (beg == end) return;

    float m = -1e30f, d = 0.f;
    float acc[8];
#pragma unroll
    for (int i = 0; i < 8; i++) acc[i] = 0.f;

    const __half* kvbase = g_qkvs + 256 + head * 128 + c;

    for (int j0 = beg; j0 < end; j0 += 32) {
        int idx = j0 + lane;
        int sreg = (idx < end) ? g_csr_src[idx] : 0;
        int cnt = min(32, end - j0);
        int t = 0;
        for (; t + 2 <= cnt; t += 2) {
            int s0 = __shfl_sync(0xFFFFFFFFu, sreg, t);
            int s1 = __shfl_sync(0xFFFFFFFFu, sreg, t + 1);
            const __half* kp0 = kvbase + (size_t)s0 * QS;
            const __half* kp1 = kvbase + (size_t)s1 * QS;
            uint4 ku0 = *(const uint4*)kp0;
            uint4 ku1 = *(const uint4*)kp1;
            uint4 vu0 = *(const uint4*)(kp0 + 256);
            uint4 vu1 = *(const uint4*)(kp1 + 256);
            float k0[8], k1[8], v0[8], v1[8];
            cvt8(k0, ku0); cvt8(k1, ku1);
            cvt8(v0, vu0); cvt8(v1, vu1);
            float l0 = q[0]*k0[0] + q[1]*k0[1] + q[2]*k0[2] + q[3]*k0[3]
                     + q[4]*k0[4] + q[5]*k0[5] + q[6]*k0[6] + q[7]*k0[7];
            float l1 = q[0]*k1[0] + q[1]*k1[1] + q[2]*k1[2] + q[3]*k1[3]
                     + q[4]*k1[4] + q[5]*k1[5] + q[6]*k1[6] + q[7]*k1[7];
#pragma unroll
            for (int o = 8; o; o >>= 1) {
                l0 += __shfl_xor_sync(0xFFFFFFFFu, l0, o);
                l1 += __shfl_xor_sync(0xFFFFFFFFu, l1, o);
            }
            float mn = fmaxf(m, l0);
            float s = __expf(m - mn);
            float wgt = __expf(l0 - mn);
            d = d * s + wgt;
#pragma unroll
            for (int i = 0; i < 8; i++) acc[i] = acc[i] * s + wgt * v0[i];
            m = mn;
            mn = fmaxf(m, l1);
            s = __expf(m - mn);
            wgt = __expf(l1 - mn);
            d = d * s + wgt;
#pragma unroll
            for (int i = 0; i < 8; i++) acc[i] = acc[i] * s + wgt * v1[i];
            m = mn;
        }
        if (t < cnt) {
            int s0 = __shfl_sync(0xFFFFFFFFu, sreg, t);
            const __half* kp0 = kvbase + (size_t)s0 * QS;
            float k0[8], v0[8];
            cvt8(k0, *(const uint4*)kp0);
            cvt8(v0, *(const uint4*)(kp0 + 256));
            float l0 = q[0]*k0[0] + q[1]*k0[1] + q[2]*k0[2] + q[3]*k0[3]
                     + q[4]*k0[4] + q[5]*k0[5] + q[6]*k0[6] + q[7]*k0[7];
#pragma unroll
            for (int o = 8; o; o >>= 1) l0 += __shfl_xor_sync(0xFFFFFFFFu, l0, o);
            float mn = fmaxf(m, l0);
            float s = __expf(m - mn);
            float wgt = __expf(l0 - mn);
            d = d * s + wgt;
#pragma unroll
            for (int i = 0; i < 8; i++) acc[i] = acc[i] * s + wgt * v0[i];
            m = mn;
        }
    }

    float inv = 1.f / fmaxf(d, 1e-16f);
    __half* op = g_qkvs + row + 768 + head * 128 + c;
    float o[8];
    cvt8(o, *(const uint4*)op);
    uint4 u;
    __half2* uh = (__half2*)&u;
#pragma unroll
    for (int i = 0; i < 4; i++)
        uh[i] = __float22half2_rn(make_float2(o[2 * i] + acc[2 * i] * inv,
                                              o[2 * i + 1] + acc[2 * i + 1] * inv));
    *(uint4*)op = u;
}

// ---------------- fp16 tensor GEMM: C[M,N] = A[M,K] @ Bh[N,K]^T (+bias) --------
// A fp16 in gmem. 128x128 tile, BK=32, 4-stage cp.async pipeline (prefetch 3
// ahead, wait_group 2), 8 warps, ONE __syncthreads per k-iteration.
// flags low 3 bits: 0=bias, 1=bias+relu, 2=no bias + column stats,
//                   3=C=alpha*C+beta*(acc+bias). bit 4 (16): C is fp16.
__global__ void __launch_bounds__(256, 2)
gemm(const __half* __restrict__ Ah, int lda,
     const __half* __restrict__ Bh,
     const float* __restrict__ bias,
     void* __restrict__ Cptr, int ldc,
     int M, int N, int K, int flags,
     float* __restrict__ stats,
     const float* __restrict__ alpha, const float* __restrict__ beta)
{
    extern __shared__ __half smh[];
    const unsigned ASZ = 128 * 40 * 2;          // bytes per stage per operand
    const unsigned B_OFF = 4 * ASZ;             // B stages follow 4 A stages
    unsigned s_base = (unsigned)__cvta_generic_to_shared(smh);

    const int tid = threadIdx.x, lane = tid & 31, w = tid >> 5;
    const int m0 = blockIdx.y * 128, n0 = blockIdx.x * 128;
    const int wm = (w & 3) * 32, wn = (w >> 2) * 64;
    const int g = lane >> 2, tg = lane & 3;

    const int cr = tid >> 1;             // copy row 0..127
    const int ch = (tid & 1) * 16;       // half-col base

    const unsigned a_loff = ((lane & 15) * 40 + (lane >> 4) * 8) * 2;
    const int bm = lane >> 3;
    const unsigned b_loff = (((bm >> 1) * 8 + (lane & 7)) * 40 + (bm & 1) * 8) * 2;

    float acc[2][8][4];
#pragma unroll
    for (int a = 0; a < 2; a++)
#pragma unroll
        for (int b = 0; b < 8; b++)
#pragma unroll
            for (int c = 0; c < 4; c++) acc[a][b][c] = 0.f;

#define CP_STAGE(K0, ST)                                                        \
    {                                                                           \
        int grow = m0 + cr;                                                     \
        int predA = (grow < M) ? 16 : 0;                                        \
        const __half* srcA = Ah + (size_t)((grow < M) ? grow : (M - 1)) * lda + (K0) + ch; \
        unsigned dstA = s_base + (ST) * ASZ + (cr * 40 + ch) * 2;               \
        asm volatile("cp.async.cg.shared.global [%0], [%1], 16, %2;"            \
                     :: "r"(dstA), "l"(srcA), "r"(predA));                      \
        asm volatile("cp.async.cg.shared.global [%0], [%1], 16, %2;"            \
                     :: "r"(dstA + 16), "l"(srcA + 8), "r"(predA));             \
        int nrow = n0 + cr;                                                     \
        int predB = (nrow < N) ? 16 : 0;                                        \
        const __half* srcB = Bh + (size_t)((nrow < N) ? nrow : (N - 1)) * K + (K0) + ch; \
        unsigned dstB = s_base + B_OFF + (ST) * ASZ + (cr * 40 + ch) * 2;       \
        asm volatile("cp.async.cg.shared.global [%0], [%1], 16, %2;"            \
                     :: "r"(dstB), "l"(srcB), "r"(predB));                      \
        asm volatile("cp.async.cg.shared.global [%0], [%1], 16, %2;"            \
                     :: "r"(dstB + 16), "l"(srcB + 8), "r"(predB));             \
        asm volatile("cp.async.commit_group;");                                 \
    }
#define COMPUTE(CUR)                                                            \
    {                                                                           \
        const unsigned aS = s_base + (CUR) * ASZ + wm * 80 + a_loff;            \
        const unsigned bS = s_base + B_OFF + (CUR) * ASZ + wn * 80 + b_loff;    \
        _Pragma("unroll")                                                       \
        for (int kk = 0; kk < 32; kk += 16) {                                   \
            unsigned a0[4], a1[4], bf[8][2];                                    \
            ldsm4(a0[0], a0[1], a0[2], a0[3], aS + kk * 2);                     \
            ldsm4(a1[0], a1[1], a1[2], a1[3], aS + 16 * 80 + kk * 2);           \
            _Pragma("unroll")                                                   \
            for (int p = 0; p < 4; p++) {                                       \
                unsigned r0, r1, r2, r3;                                        \
                ldsm4(r0, r1, r2, r3, bS + p * 16 * 80 + kk * 2);               \
                bf[2 * p][0] = r0;     bf[2 * p][1] = r1;                       \
                bf[2 * p + 1][0] = r2; bf[2 * p + 1][1] = r3;                   \
            }                                                                   \
            _Pragma("unroll")                                                   \
            for (int nj = 0; nj < 8; nj++) {                                    \
                mma16(acc[0][nj], a0, bf[nj]);                                  \
                mma16(acc[1][nj], a1, bf[nj]);                                  \
            }                                                                   \
        }                                                                       \
    }

    const int T = K >> 5;    // all call sites have T >= 8

    CP_STAGE(0, 0);
    CP_STAGE(32, 1);
    CP_STAGE(64, 2);

    int st = 0;              // stage of current iteration
    for (int it = 0; it < T; ++it) {
        if (it + 1 < T) {
            asm volatile("cp.async.wait_group 2;");
        } else {
            asm volatile("cp.async.wait_group 0;");
        }
        __syncthreads();
        if (it + 3 < T) {
            int stn = st + 3; if (stn >= 4) stn -= 4;
            CP_STAGE((it + 3) << 5, stn);
        }
        COMPUTE(st);
        if (++st == 4) st = 0;
    }
    __syncthreads();

    // ---- epilogue ----
    const int fbase = flags & 7;
    const bool ch16 = (flags & 16) != 0;
    float alp = 0.f, bet = 0.f;
    if (fbase == 3) { alp = alpha[0]; bet = beta[0]; }
    float* Cf = (float*)Cptr;
    __half* Chf = (__half*)Cptr;

#pragma unroll
    for (int mi = 0; mi < 2; mi++) {
        int r0 = m0 + wm + mi * 16 + g;
        int r1 = r0 + 8;
#pragma unroll
        for (int nj = 0; nj < 8; nj++) {
            int gc = n0 + wn + nj * 8 + 2 * tg;
            if (gc >= N) continue;
            float bx = 0.f, by = 0.f;
            if (fbase != 2) { bx = bias[gc]; by = bias[gc + 1]; }
            float2 v0 = make_float2(acc[mi][nj][0] + bx, acc[mi][nj][1] + by);
            float2 v1 = make_float2(acc[mi][nj][2] + bx, acc[mi][nj][3] + by);
            if (fbase == 1) {
                v0.x = fmaxf(v0.x, 0.f); v0.y = fmaxf(v0.y, 0.f);
                v1.x = fmaxf(v1.x, 0.f); v1.y = fmaxf(v1.y, 0.f);
            }
            if (fbase == 3) {
                if (r0 < M) {
                    float2 o = __half22float2(*(__half2*)(Chf + (size_t)r0 * ldc + gc));
                    v0.x = alp * o.x + bet * v0.x; v0.y = alp * o.y + bet * v0.y;
                }
                if (r1 < M) {
                    float2 o = __half22float2(*(__half2*)(Chf + (size_t)r1 * ldc + gc));
                    v1.x = alp * o.x + bet * v1.x; v1.y = alp * o.y + bet * v1.y;
                }
            }
            if (ch16) {
                if (r0 < M) *(__half2*)(Chf + (size_t)r0 * ldc + gc) = __float22half2_rn(v0);
                if (r1 < M) *(__half2*)(Chf + (size_t)r1 * ldc + gc) = __float22half2_rn(v1);
            } else {
                if (r0 < M) *(float2*)(Cf + (size_t)r0 * ldc + gc) = v0;
                if (r1 < M) *(float2*)(Cf + (size_t)r1 * ldc + gc) = v1;
            }
        }
    }

    if (fbase == 2) {
#pragma unroll
        for (int nj = 0; nj < 8; nj++) {
            int gc = n0 + wn + nj * 8 + 2 * tg;
            float sx = acc[0][nj][0] + acc[0][nj][2] + acc[1][nj][0] + acc[1][nj][2];
            float sy = acc[0][nj][1] + acc[0][nj][3] + acc[1][nj][1] + acc[1][nj][3];
            float qx = acc[0][nj][0] * acc[0][nj][0] + acc[0][nj][2] * acc[0][nj][2]
                     + acc[1][nj][0] * acc[1][nj][0] + acc[1][nj][2] * acc[1][nj][2];
            float qy = acc[0][nj][1] * acc[0][nj][1] + acc[0][nj][3] * acc[0][nj][3]
                     + acc[1][nj][1] * acc[1][nj][1] + acc[1][nj][3] * acc[1][nj][3];
#pragma unroll
            for (int o = 4; o < 32; o <<= 1) {
                sx += __shfl_xor_sync(0xFFFFFFFFu, sx, o);
                sy += __shfl_xor_sync(0xFFFFFFFFu, sy, o);
                qx += __shfl_xor_sync(0xFFFFFFFFu, qx, o);
                qy += __shfl_xor_sync(0xFFFFFFFFu, qy, o);
            }
            if (lane < 4) redAdd4(&stats[gc * 2], sx, qx, sy, qy);
        }
    }
#undef CP_STAGE
#undef COMPUTE
}

// ---------------- batchnorm ----------------------------------------------------
__global__ void bn_finalize(const float* __restrict__ stats,
                            float* __restrict__ mu, float* __restrict__ rsig)
{
    int c = threadIdx.x + blockIdx.x * blockDim.x;
    if (c >= HID) return;
    float m = stats[c * 2] * (1.f / NN);
    float var = stats[c * 2 + 1] * (1.f / NN) - m * m;
    mu[c] = m;
    rsig[c] = rsqrtf(var + 1e-5f);
}

__global__ void bn_apply_sigmoid(__half* __restrict__ X,
                                 const float* __restrict__ mu, const float* __restrict__ rsig,
                                 const float* __restrict__ g, const float* __restrict__ be)
{
    size_t i = (size_t)blockIdx.x * blockDim.x + threadIdx.x;
    if (i >= (size_t)NN * HID / 4) return;
    size_t base = i * 4;
    int c = (int)(base & (HID - 1));
    float4 x = ld4h(X + base);
    float4 y;
    y.x = (x.x - mu[c])     * rsig[c]     * g[c]     + be[c];
    y.y = (x.y - mu[c + 1]) * rsig[c + 1] * g[c + 1] + be[c + 1];
    y.z = (x.z - mu[c + 2]) * rsig[c + 2] * g[c + 2] + be[c + 2];
    y.w = (x.w - mu[c + 3]) * rsig[c + 3] * g[c + 3] + be[c + 3];
    y.x = 1.f / (1.f + expf(-y.x));
    y.y = 1.f / (1.f + expf(-y.y));
    y.z = 1.f / (1.f + expf(-y.z));
    y.w = 1.f / (1.f + expf(-y.w));
    st4h(X + base, y);
}

// ---------------- launch --------------------------------------------------------
extern "C" void kernel_launch(void* const* d_in, const int* in_sizes, int n_in,
                              void* d_out, int out_size)
{
    const float* x_gsage = (const float*)d_in[0];
    const int*   ei      = (const int*)d_in[1];
    const float* x_mlp   = (const float*)d_in[2];
    const float* Wq = (const float*)d_in[3];  const float* bq = (const float*)d_in[4];
    const float* Wk = (const float*)d_in[5];  const float* bk = (const float*)d_in[6];
    const float* Wv = (const float*)d_in[7];  const float* bv = (const float*)d_in[8];
    const float* Ws = (const float*)d_in[9];  const float* bs = (const float*)d_in[10];
    const float* W1 = (const float*)d_in[11];
    const float* g1 = (const float*)d_in[13]; const float* be1 = (const float*)d_in[14];
    const float* W2 = (const float*)d_in[15];
    const float* g2 = (const float*)d_in[17]; const float* be2 = (const float*)d_in[18];
    const float* W3 = (const float*)d_in[19]; const float* b3 = (const float*)d_in[20];
    const float* alpha = (const float*)d_in[21];
    const float* beta  = (const float*)d_in[22];
    const float* Wc1 = (const float*)d_in[23]; const float* bc1 = (const float*)d_in[24];
    const float* Wc2 = (const float*)d_in[25]; const float* bc2 = (const float*)d_in[26];
    float* out = (float*)d_out;

    __half *qkvs, *h1, *h2, *wh, *xg, *xm;
    float *bcat, *stats1, *stats2, *mu1, *rsig1, *mu2, *rsig2;
    cudaGetSymbolAddress((void**)&qkvs, g_qkvs);
    cudaGetSymbolAddress((void**)&h1, g_h1);
    cudaGetSymbolAddress((void**)&h2, g_h2);
    cudaGetSymbolAddress((void**)&wh, g_wh);
    cudaGetSymbolAddress((void**)&xg, g_xg);
    cudaGetSymbolAddress((void**)&xm, g_xm);
    cudaGetSymbolAddress((void**)&bcat, g_bcat);
    cudaGetSymbolAddress((void**)&stats1, g_stats1);
    cudaGetSymbolAddress((void**)&stats2, g_stats2);
    cudaGetSymbolAddress((void**)&mu1, g_mu1);
    cudaGetSymbolAddress((void**)&rsig1, g_rsig1);
    cudaGetSymbolAddress((void**)&mu2, g_mu2);
    cudaGetSymbolAddress((void**)&rsig2, g_rsig2);

    static cudaStream_t s1 = nullptr, s2 = nullptr;
    static cudaEvent_t evStart, evPre, evCSR, evMLP;
    if (!s1) {
        cudaStreamCreateWithFlags(&s1, cudaStreamNonBlocking);
        cudaStreamCreateWithFlags(&s2, cudaStreamNonBlocking);
        cudaEventCreateWithFlags(&evStart, cudaEventDisableTiming);
        cudaEventCreateWithFlags(&evPre,  cudaEventDisableTiming);
        cudaEventCreateWithFlags(&evCSR,  cudaEventDisableTiming);
        cudaEventCreateWithFlags(&evMLP,  cudaEventDisableTiming);
        cudaFuncSetAttribute(gemm, cudaFuncAttributeMaxDynamicSharedMemorySize, 81920);
    }

    const int SMB = 81920;             // 4 stages x (A+B) x 10240 B
    const int MB = (NN + 127) / 128;
    const int NXE = NN * 256;          // elems per x matrix
    dim3 blk(256);

    cudaEventRecord(evStart, 0);

    // ---- main: preconv(1) + init(2) + cvt_xg(3), then the big GEMM at (4) so
    // the ncu -s window captures it ----
    preconv<<<(WTF_TOT + QS + 255) / 256, blk>>>(Wq, Wk, Wv, Ws, W1, W2, W3, Wc1, Wc2,
                                                 bq, bk, bv, bs);
    init_stats<<<4, blk>>>();
    cvt_f2h<<<(NXE / 8 + 255) / 256, blk>>>(x_gsage, xg, NXE);
    cudaEventRecord(evPre, 0);

    // (4) fused q|k|v|skip projection — the biggest GEMM
    gemm<<<dim3(8, MB), blk, SMB>>>(xg, 256, wh + OFF_QKVS, bcat, qkvs, QS,
                                    NN, 1024, 256, 0 | 16, nullptr, nullptr, nullptr);

    // ---- fork s1: CSR build (runs from t=0, overlaps everything) ----
    cudaStreamWaitEvent(s1, evStart, 0);
    zero_deg<<<(NN + 255) / 256, blk, 0, s1>>>();
    count_deg<<<(EE + 255) / 256, blk, 0, s1>>>(ei);
    deg_block_sums<<<NBLK, blk, 0, s1>>>();
    scan_bsums<<<1, blk, 0, s1>>>();
    write_offsets<<<NBLK, blk, 0, s1>>>();
    scatter_edges<<<(EE + 255) / 256, blk, 0, s1>>>(ei);
    cudaEventRecord(evCSR, s1);

    // ---- fork s2: MLP branch (convert + GEMMs), overlaps GNN ----
    cudaStreamWaitEvent(s2, evPre, 0);
    cvt_f2h<<<(NXE / 8 + 255) / 256, blk, 0, s2>>>(x_mlp, xm, NXE);
    gemm<<<dim3(4, MB), blk, SMB, s2>>>(xm, 256, wh + OFF_W1, nullptr, h1, HID,
                                        NN, HID, 256, 2 | 16, stats1, nullptr, nullptr);
    bn_finalize<<<2, blk, 0, s2>>>(stats1, mu1, rsig1);
    bn_apply_sigmoid<<<((size_t)NN * HID / 4 + 255) / 256, blk, 0, s2>>>(h1, mu1, rsig1, g1, be1);
    gemm<<<dim3(4, MB), blk, SMB, s2>>>(h1, HID, wh + OFF_W2, nullptr, h2, HID,
                                        NN, HID, HID, 2 | 16, stats2, nullptr, nullptr);
    bn_finalize<<<2, blk, 0, s2>>>(stats2, mu2, rsig2);
    bn_apply_sigmoid<<<((size_t)NN * HID / 4 + 255) / 256, blk, 0, s2>>>(h2, mu2, rsig2, g2, be2);
    cudaEventRecord(evMLP, s2);

    // ---- main: attention (needs qkvs + CSR) ----
    cudaStreamWaitEvent(0, evCSR, 0);
    attn_fused<<<(NN + 7) / 8, blk>>>();

    // ---- join: W3 needs h2 (s2) and hg (main) ----
    cudaStreamWaitEvent(0, evMLP, 0);
    gemm<<<dim3(2, MB), blk, SMB>>>(h2, HID, wh + OFF_W3, b3, qkvs + 768, QS,
                                    NN, HC, HID, 3 | 16, nullptr, alpha, beta);

    // classifier
    gemm<<<dim3(4, MB), blk, SMB>>>(qkvs + 768, QS, wh + OFF_WC1, bc1, h1, HID,
                                    NN, HID, HC, 1 | 16, nullptr, nullptr, nullptr);
    gemm<<<dim3(1, MB), blk, SMB>>>(h1, HID, wh + OFF_WC2, bc2, out, NCLS,
                                    NN, NCLS, HID, 0, nullptr, nullptr, nullptr);
}

// round 15
// speedup vs baseline: 1.0119x; 1.0119x over previous
#include <cuda_runtime.h>
#include <cuda_fp16.h>
#include <math.h>
#include <stdint.h>

#define NN 50000
#define EE 800000
#define HID 512
#define HC 256
#define NCLS 40
#define QS 1024     // interleaved qkv+skip stride (halfs)
#define NBLK 196    // ceil(NN/256)

// weight-buffer offsets (fp16-converted, row-major [N][K])
#define OFF_QKVS 0
#define OFF_W1   262144
#define OFF_W2   393216
#define OFF_W3   655360
#define OFF_WC1  786432
#define OFF_WC2  917504
#define WTF_TOT  937984

// ---------------- scratch ----------------------------------------------------
__device__ __half g_qkvs[(size_t)NN * QS];  // q[0,256) k[256,512) v[512,768) hg[768,1024)
__device__ __half g_h1[(size_t)NN * HID];
__device__ __half g_h2[(size_t)NN * HID];
__device__ __half g_xg[(size_t)NN * 256];   // fp16 copy of x_gsage
__device__ __half g_xm[(size_t)NN * 256];   // fp16 copy of x_mlp
__device__ int    g_deg[NN];
__device__ int    g_off[NN + 1];
__device__ int    g_cursor[NN];
__device__ int    g_csr_src[EE];
__device__ int    g_bsum[256];
__device__ int    g_bpref[256];
__device__ float  g_stats1[HID * 2];        // interleaved sum, sumsq
__device__ float  g_stats2[HID * 2];
__device__ float  g_mu1[HID], g_rsig1[HID], g_mu2[HID], g_rsig2[HID];
__device__ __half g_wh[WTF_TOT];
__device__ float  g_bcat[QS];

// ---------------- helpers ----------------------------------------------------
__device__ __forceinline__ void redAdd4(float* p, float a, float b, float c, float d) {
    asm volatile("red.global.add.v4.f32 [%0], {%1,%2,%3,%4};"
                 :: "l"(p), "f"(a), "f"(b), "f"(c), "f"(d) : "memory");
}
__device__ __forceinline__ float4 ld4h(const __half* p) {
    uint2 u = *(const uint2*)p;
    __half2 h0 = *(__half2*)&u.x, h1 = *(__half2*)&u.y;
    float2 a = __half22float2(h0), b = __half22float2(h1);
    return make_float4(a.x, a.y, b.x, b.y);
}
__device__ __forceinline__ void st4h(__half* p, float4 v) {
    uint2 u;
    __half2 h0 = __float22half2_rn(make_float2(v.x, v.y));
    __half2 h1 = __float22half2_rn(make_float2(v.z, v.w));
    u.x = *(unsigned*)&h0; u.y = *(unsigned*)&h1;
    *(uint2*)p = u;
}
__device__ __forceinline__ void cvt8(float* f, uint4 u) {
    __half2* h = (__half2*)&u;
#pragma unroll
    for (int i = 0; i < 4; i++) {
        float2 t = __half22float2(h[i]);
        f[2 * i] = t.x; f[2 * i + 1] = t.y;
    }
}
__device__ __forceinline__ void ldsm4(unsigned& r0, unsigned& r1, unsigned& r2, unsigned& r3,
                                      unsigned addr) {
    asm volatile("ldmatrix.sync.aligned.m8n8.x4.shared.b16 {%0,%1,%2,%3}, [%4];"
                 : "=r"(r0), "=r"(r1), "=r"(r2), "=r"(r3) : "r"(addr));
}
__device__ __forceinline__ void mma16(float* d, const unsigned* a, const unsigned* b) {
    asm volatile("mma.sync.aligned.m16n8k16.row.col.f32.f16.f16.f32 "
                 "{%0,%1,%2,%3},{%4,%5,%6,%7},{%8,%9},{%0,%1,%2,%3};"
                 : "+f"(d[0]), "+f"(d[1]), "+f"(d[2]), "+f"(d[3])
                 : "r"(a[0]), "r"(a[1]), "r"(a[2]), "r"(a[3]), "r"(b[0]), "r"(b[1]));
}

// ---------------- preconvert weights to fp16 + concat biases -----------------
__global__ void preconv(const float* __restrict__ Wq, const float* __restrict__ Wk,
                        const float* __restrict__ Wv, const float* __restrict__ Ws,
                        const float* __restrict__ W1, const float* __restrict__ W2,
                        const float* __restrict__ W3, const float* __restrict__ Wc1,
                        const float* __restrict__ Wc2,
                        const float* __restrict__ bq, const float* __restrict__ bk,
                        const float* __restrict__ bv, const float* __restrict__ bs)
{
    int i = blockIdx.x * 256 + threadIdx.x;
    if (i < WTF_TOT) {
        float v;
        if (i < OFF_W1) {
            int wsel = i >> 16, idx = i & 65535;
            const float* src = (wsel == 0) ? Wq : (wsel == 1) ? Wk : (wsel == 2) ? Wv : Ws;
            v = src[idx];
        } else if (i < OFF_W2)  v = W1[i - OFF_W1];
        else if (i < OFF_W3)    v = W2[i - OFF_W2];
        else if (i < OFF_WC1)   v = W3[i - OFF_W3];
        else if (i < OFF_WC2)   v = Wc1[i - OFF_WC1];
        else                    v = Wc2[i - OFF_WC2];
        g_wh[i] = __float2half_rn(v);
    } else if (i < WTF_TOT + QS) {
        int j = i - WTF_TOT;
        int sel = j >> 8, idx = j & 255;
        const float* src = (sel == 0) ? bq : (sel == 1) ? bk : (sel == 2) ? bv : bs;
        g_bcat[j] = src[idx];
    }
}

// fp32 -> fp16 bulk convert (8 elems/thread)
__global__ void __launch_bounds__(256)
cvt_f2h(const float* __restrict__ X, __half* __restrict__ Y, int n)
{
    int i = (blockIdx.x * 256 + threadIdx.x) * 8;
    if (i >= n) return;
    float4 a = *(const float4*)(X + i);
    float4 b = *(const float4*)(X + i + 4);
    uint4 u;
    __half2 h;
    h = __float22half2_rn(make_float2(a.x, a.y)); u.x = *(unsigned*)&h;
    h = __float22half2_rn(make_float2(a.z, a.w)); u.y = *(unsigned*)&h;
    h = __float22half2_rn(make_float2(b.x, b.y)); u.z = *(unsigned*)&h;
    h = __float22half2_rn(make_float2(b.z, b.w)); u.w = *(unsigned*)&h;
    *(uint4*)(Y + i) = u;
}

__global__ void init_stats() {
    int i = blockIdx.x * blockDim.x + threadIdx.x;
    if (i < HID * 2) {
        g_stats1[i] = 0.f;
        g_stats2[i] = 0.f;
    }
}

// ---------------- CSR build (parallel scan) -------------------------------------
__global__ void zero_deg() {
    int i = blockIdx.x * blockDim.x + threadIdx.x;
    if (i < NN) g_deg[i] = 0;
}
__global__ void count_deg(const int* __restrict__ ei) {
    int e = blockIdx.x * blockDim.x + threadIdx.x;
    if (e >= EE) return;
    atomicAdd(&g_deg[ei[EE + e]], 1);
}
__global__ void __launch_bounds__(256)
deg_block_sums() {
    int i = blockIdx.x * 256 + threadIdx.x;
    int v = (i < NN) ? g_deg[i] : 0;
#pragma unroll
    for (int o = 16; o; o >>= 1) v += __shfl_xor_sync(0xFFFFFFFFu, v, o);
    __shared__ int ws[8];
    if ((threadIdx.x & 31) == 0) ws[threadIdx.x >> 5] = v;
    __syncthreads();
    if (threadIdx.x < 8) {
        int s = ws[threadIdx.x];
#pragma unroll
        for (int o = 4; o; o >>= 1) s += __shfl_xor_sync(0xFFu, s, o);
        if (threadIdx.x == 0) g_bsum[blockIdx.x] = s;
    }
}
__global__ void __launch_bounds__(256)
scan_bsums() {
    __shared__ int sm[256];
    int t = threadIdx.x;
    int v = (t < NBLK) ? g_bsum[t] : 0;
    sm[t] = v;
    __syncthreads();
#pragma unroll
    for (int s = 1; s < 256; s <<= 1) {
        int u = (t >= s) ? sm[t - s] : 0;
        __syncthreads();
        sm[t] += u;
        __syncthreads();
    }
    if (t < NBLK) g_bpref[t] = sm[t] - v;
}
__global__ void __launch_bounds__(256)
write_offsets() {
    __shared__ int sm[256];
    int t = threadIdx.x;
    int i = blockIdx.x * 256 + t;
    int v = (i < NN) ? g_deg[i] : 0;
    sm[t] = v;
    __syncthreads();
#pragma unroll
    for (int s = 1; s < 256; s <<= 1) {
        int u = (t >= s) ? sm[t - s] : 0;
        __syncthreads();
        sm[t] += u;
        __syncthreads();
    }
    if (i < NN) {
        int off = g_bpref[blockIdx.x] + sm[t];
        g_off[i + 1] = off;
        g_cursor[i] = off - v;
    }
    if (i == 0) g_off[0] = 0;
}
__global__ void scatter_edges(const int* __restrict__ ei) {
    int e = blockIdx.x * blockDim.x + threadIdx.x;
    if (e >= EE) return;
    int src = ei[e];
    int dst = ei[EE + e];
    int pos = atomicAdd(&g_cursor[dst], 1);
    g_csr_src[pos] = src;
}

// ---------------- fused attention: warp per node, unroll-4 online softmax ------
__global__ void __launch_bounds__(256)
attn_fused()
{
    int nid = blockIdx.x * 8 + (threadIdx.x >> 5);
    if (nid >= NN) return;
    int lane = threadIdx.x & 31;
    int head = lane >> 4;
    int c = (lane & 15) * 8;

    const size_t row = (size_t)nid * QS;
    float q[8];
    cvt8(q, *(const uint4*)(g_qkvs + row + head * 128 + c));
#pragma unroll
    for (int i = 0; i < 8; i++) q[i] *= 0.08838834764831845f;

    int beg = g_off[nid], end = g_off[nid + 1];
    if (beg == end) return;

    float m = -1e30f, d = 0.f;
    float acc[8];
#pragma unroll
    for (int i = 0; i < 8; i++) acc[i] = 0.f;

    const __half* kvbase = g_qkvs + 256 + head * 128 + c;

    for (int j0 = beg; j0 < end; j0 += 32) {
        int idx = j0 + lane;
        int sreg = (idx < end) ? g_csr_src[idx] : 0;
        int cnt = min(32, end - j0);
        int t = 0;
        for (; t + 4 <= cnt; t += 4) {
            // batch 8 independent 16B loads (4 edges x {k,v}) for MLP
            int s0 = __shfl_sync(0xFFFFFFFFu, sreg, t);
            int s1 = __shfl_sync(0xFFFFFFFFu, sreg, t + 1);
            int s2 = __shfl_sync(0xFFFFFFFFu, sreg, t + 2);
            int s3 = __shfl_sync(0xFFFFFFFFu, sreg, t + 3);
            const __half* p0 = kvbase + (size_t)s0 * QS;
            const __half* p1 = kvbase + (size_t)s1 * QS;
            const __half* p2 = kvbase + (size_t)s2 * QS;
            const __half* p3 = kvbase + (size_t)s3 * QS;
            uint4 ku0 = *(const uint4*)p0;
            uint4 ku1 = *(const uint4*)p1;
            uint4 ku2 = *(const uint4*)p2;
            uint4 ku3 = *(const uint4*)p3;
            uint4 vu0 = *(const uint4*)(p0 + 256);
            uint4 vu1 = *(const uint4*)(p1 + 256);
            uint4 vu2 = *(const uint4*)(p2 + 256);
            uint4 vu3 = *(const uint4*)(p3 + 256);
            float kf[8], l0, l1, l2, l3;
            cvt8(kf, ku0);
            l0 = q[0]*kf[0]+q[1]*kf[1]+q[2]*kf[2]+q[3]*kf[3]
               + q[4]*kf[4]+q[5]*kf[5]+q[6]*kf[6]+q[7]*kf[7];
            cvt8(kf, ku1);
            l1 = q[0]*kf[0]+q[1]*kf[1]+q[2]*kf[2]+q[3]*kf[3]
               + q[4]*kf[4]+q[5]*kf[5]+q[6]*kf[6]+q[7]*kf[7];
            cvt8(kf, ku2);
            l2 = q[0]*kf[0]+q[1]*kf[1]+q[2]*kf[2]+q[3]*kf[3]
               + q[4]*kf[4]+q[5]*kf[5]+q[6]*kf[6]+q[7]*kf[7];
            cvt8(kf, ku3);
            l3 = q[0]*kf[0]+q[1]*kf[1]+q[2]*kf[2]+q[3]*kf[3]
               + q[4]*kf[4]+q[5]*kf[5]+q[6]*kf[6]+q[7]*kf[7];
#pragma unroll
            for (int o = 8; o; o >>= 1) {
                l0 += __shfl_xor_sync(0xFFFFFFFFu, l0, o);
                l1 += __shfl_xor_sync(0xFFFFFFFFu, l1, o);
                l2 += __shfl_xor_sync(0xFFFFFFFFu, l2, o);
                l3 += __shfl_xor_sync(0xFFFFFFFFu, l3, o);
            }
            float vf[8], mn, s, wgt;
            mn = fmaxf(m, l0); s = __expf(m - mn); wgt = __expf(l0 - mn);
            d = d * s + wgt; cvt8(vf, vu0);
#pragma unroll
            for (int i = 0; i < 8; i++) acc[i] = acc[i] * s + wgt * vf[i];
            m = mn;
            mn = fmaxf(m, l1); s = __expf(m - mn); wgt = __expf(l1 - mn);
            d = d * s + wgt; cvt8(vf, vu1);
#pragma unroll
            for (int i = 0; i < 8; i++) acc[i] = acc[i] * s + wgt * vf[i];
            m = mn;
            mn = fmaxf(m, l2); s = __expf(m - mn); wgt = __expf(l2 - mn);
            d = d * s + wgt; cvt8(vf, vu2);
#pragma unroll
            for (int i = 0; i < 8; i++) acc[i] = acc[i] * s + wgt * vf[i];
            m = mn;
            mn = fmaxf(m, l3); s = __expf(m - mn); wgt = __expf(l3 - mn);
            d = d * s + wgt; cvt8(vf, vu3);
#pragma unroll
            for (int i = 0; i < 8; i++) acc[i] = acc[i] * s + wgt * vf[i];
            m = mn;
        }
        for (; t < cnt; t++) {
            int s0 = __shfl_sync(0xFFFFFFFFu, sreg, t);
            const __half* kp0 = kvbase + (size_t)s0 * QS;
            float k0[8], v0[8];
            cvt8(k0, *(const uint4*)kp0);
            cvt8(v0, *(const uint4*)(kp0 + 256));
            float l0 = q[0]*k0[0]+q[1]*k0[1]+q[2]*k0[2]+q[3]*k0[3]
                     + q[4]*k0[4]+q[5]*k0[5]+q[6]*k0[6]+q[7]*k0[7];
#pragma unroll
            for (int o = 8; o; o >>= 1) l0 += __shfl_xor_sync(0xFFFFFFFFu, l0, o);
            float mn = fmaxf(m, l0);
            float s = __expf(m - mn);
            float wgt = __expf(l0 - mn);
            d = d * s + wgt;
#pragma unroll
            for (int i = 0; i < 8; i++) acc[i] = acc[i] * s + wgt * v0[i];
            m = mn;
        }
    }

    float inv = 1.f / fmaxf(d, 1e-16f);
    __half* op = g_qkvs + row + 768 + head * 128 + c;
    float o[8];
    cvt8(o, *(const uint4*)op);
    uint4 u;
    __half2* uh = (__half2*)&u;
#pragma unroll
    for (int i = 0; i < 4; i++)
        uh[i] = __float22half2_rn(make_float2(o[2 * i] + acc[2 * i] * inv,
                                              o[2 * i + 1] + acc[2 * i + 1] * inv));
    *(uint4*)op = u;
}

// ---------------- fp16 tensor GEMM: C[M,N] = A[M,K] @ Bh[N,K]^T (+bias) --------
// A fp16 in gmem. 128x128 tile, BK=32, 3-stage cp.async pipeline, 8 warps,
// ONE __syncthreads per k-iteration.  (R13-proven configuration)
// flags low 3 bits: 0=bias, 1=bias+relu, 2=no bias + column stats,
//                   3=C=alpha*C+beta*(acc+bias). bit 4 (16): C is fp16.
__global__ void __launch_bounds__(256, 2)
gemm(const __half* __restrict__ Ah, int lda,
     const __half* __restrict__ Bh,
     const float* __restrict__ bias,
     void* __restrict__ Cptr, int ldc,
     int M, int N, int K, int flags,
     float* __restrict__ stats,
     const float* __restrict__ alpha, const float* __restrict__ beta)
{
    extern __shared__ __half smh[];
    const unsigned ASZ = 128 * 40 * 2;          // bytes per stage per operand
    const unsigned B_OFF = 3 * ASZ;             // B stages follow 3 A stages
    unsigned s_base = (unsigned)__cvta_generic_to_shared(smh);

    const int tid = threadIdx.x, lane = tid & 31, w = tid >> 5;
    const int m0 = blockIdx.y * 128, n0 = blockIdx.x * 128;
    const int wm = (w & 3) * 32, wn = (w >> 2) * 64;
    const int g = lane >> 2, tg = lane & 3;

    const int cr = tid >> 1;             // copy row 0..127
    const int ch = (tid & 1) * 16;       // half-col base

    const unsigned a_loff = ((lane & 15) * 40 + (lane >> 4) * 8) * 2;
    const int bm = lane >> 3;
    const unsigned b_loff = (((bm >> 1) * 8 + (lane & 7)) * 40 + (bm & 1) * 8) * 2;

    float acc[2][8][4];
#pragma unroll
    for (int a = 0; a < 2; a++)
#pragma unroll
        for (int b = 0; b < 8; b++)
#pragma unroll
            for (int c = 0; c < 4; c++) acc[a][b][c] = 0.f;

#define CP_STAGE(K0, ST)                                                        \
    {                                                                           \
        int grow = m0 + cr;                                                     \
        int predA = (grow < M) ? 16 : 0;                                        \
        const __half* srcA = Ah + (size_t)((grow < M) ? grow : (M - 1)) * lda + (K0) + ch; \
        unsigned dstA = s_base + (ST) * ASZ + (cr * 40 + ch) * 2;               \
        asm volatile("cp.async.cg.shared.global [%0], [%1], 16, %2;"            \
                     :: "r"(dstA), "l"(srcA), "r"(predA));                      \
        asm volatile("cp.async.cg.shared.global [%0], [%1], 16, %2;"            \
                     :: "r"(dstA + 16), "l"(srcA + 8), "r"(predA));             \
        int nrow = n0 + cr;                                                     \
        int predB = (nrow < N) ? 16 : 0;                                        \
        const __half* srcB = Bh + (size_t)((nrow < N) ? nrow : (N - 1)) * K + (K0) + ch; \
        unsigned dstB = s_base + B_OFF + (ST) * ASZ + (cr * 40 + ch) * 2;       \
        asm volatile("cp.async.cg.shared.global [%0], [%1], 16, %2;"            \
                     :: "r"(dstB), "l"(srcB), "r"(predB));                      \
        asm volatile("cp.async.cg.shared.global [%0], [%1], 16, %2;"            \
                     :: "r"(dstB + 16), "l"(srcB + 8), "r"(predB));             \
        asm volatile("cp.async.commit_group;");                                 \
    }
#define COMPUTE(CUR)                                                            \
    {                                                                           \
        const unsigned aS = s_base + (CUR) * ASZ + wm * 80 + a_loff;            \
        const unsigned bS = s_base + B_OFF + (CUR) * ASZ + wn * 80 + b_loff;    \
        _Pragma("unroll")                                                       \
        for (int kk = 0; kk < 32; kk += 16) {                                   \
            unsigned a0[4], a1[4], bf[8][2];                                    \
            ldsm4(a0[0], a0[1], a0[2], a0[3], aS + kk * 2);                     \
            ldsm4(a1[0], a1[1], a1[2], a1[3], aS + 16 * 80 + kk * 2);           \
            _Pragma("unroll")                                                   \
            for (int p = 0; p < 4; p++) {                                       \
                unsigned r0, r1, r2, r3;                                        \
                ldsm4(r0, r1, r2, r3, bS + p * 16 * 80 + kk * 2);               \
                bf[2 * p][0] = r0;     bf[2 * p][1] = r1;                       \
                bf[2 * p + 1][0] = r2; bf[2 * p + 1][1] = r3;                   \
            }                                                                   \
            _Pragma("unroll")                                                   \
            for (int nj = 0; nj < 8; nj++) {                                    \
                mma16(acc[0][nj], a0, bf[nj]);                                  \
                mma16(acc[1][nj], a1, bf[nj]);                                  \
            }                                                                   \
        }                                                                       \
    }

    const int T = K >> 5;    // all call sites have T >= 8

    CP_STAGE(0, 0);
    CP_STAGE(32, 1);

    int st = 0;              // stage of current iteration
    for (int it = 0; it < T; ++it) {
        if (it + 1 < T) {
            asm volatile("cp.async.wait_group 1;");
        } else {
            asm volatile("cp.async.wait_group 0;");
        }
        __syncthreads();
        if (it + 2 < T) {
            int stn = st + 2; if (stn >= 3) stn -= 3;
            CP_STAGE((it + 2) << 5, stn);
        }
        COMPUTE(st);
        if (++st == 3) st = 0;
    }
    __syncthreads();

    // ---- epilogue ----
    const int fbase = flags & 7;
    const bool ch16 = (flags & 16) != 0;
    float alp = 0.f, bet = 0.f;
    if (fbase == 3) { alp = alpha[0]; bet = beta[0]; }
    float* Cf = (float*)Cptr;
    __half* Chf = (__half*)Cptr;

#pragma unroll
    for (int mi = 0; mi < 2; mi++) {
        int r0 = m0 + wm + mi * 16 + g;
        int r1 = r0 + 8;
#pragma unroll
        for (int nj = 0; nj < 8; nj++) {
            int gc = n0 + wn + nj * 8 + 2 * tg;
            if (gc >= N) continue;
            float bx = 0.f, by = 0.f;
            if (fbase != 2) { bx = bias[gc]; by = bias[gc + 1]; }
            float2 v0 = make_float2(acc[mi][nj][0] + bx, acc[mi][nj][1] + by);
            float2 v1 = make_float2(acc[mi][nj][2] + bx, acc[mi][nj][3] + by);
            if (fbase == 1) {
                v0.x = fmaxf(v0.x, 0.f); v0.y = fmaxf(v0.y, 0.f);
                v1.x = fmaxf(v1.x, 0.f); v1.y = fmaxf(v1.y, 0.f);
            }
            if (fbase == 3) {
                if (r0 < M) {
                    float2 o = __half22float2(*(__half2*)(Chf + (size_t)r0 * ldc + gc));
                    v0.x = alp * o.x + bet * v0.x; v0.y = alp * o.y + bet * v0.y;
                }
                if (r1 < M) {
                    float2 o = __half22float2(*(__half2*)(Chf + (size_t)r1 * ldc + gc));
                    v1.x = alp * o.x + bet * v1.x; v1.y = alp * o.y + bet * v1.y;
                }
            }
            if (ch16) {
                if (r0 < M) *(__half2*)(Chf + (size_t)r0 * ldc + gc) = __float22half2_rn(v0);
                if (r1 < M) *(__half2*)(Chf + (size_t)r1 * ldc + gc) = __float22half2_rn(v1);
            } else {
                if (r0 < M) *(float2*)(Cf + (size_t)r0 * ldc + gc) = v0;
                if (r1 < M) *(float2*)(Cf + (size_t)r1 * ldc + gc) = v1;
            }
        }
    }

    if (fbase == 2) {
#pragma unroll
        for (int nj = 0; nj < 8; nj++) {
            int gc = n0 + wn + nj * 8 + 2 * tg;
            float sx = acc[0][nj][0] + acc[0][nj][2] + acc[1][nj][0] + acc[1][nj][2];
            float sy = acc[0][nj][1] + acc[0][nj][3] + acc[1][nj][1] + acc[1][nj][3];
            float qx = acc[0][nj][0] * acc[0][nj][0] + acc[0][nj][2] * acc[0][nj][2]
                     + acc[1][nj][0] * acc[1][nj][0] + acc[1][nj][2] * acc[1][nj][2];
            float qy = acc[0][nj][1] * acc[0][nj][1] + acc[0][nj][3] * acc[0][nj][3]
                     + acc[1][nj][1] * acc[1][nj][1] + acc[1][nj][3] * acc[1][nj][3];
#pragma unroll
            for (int o = 4; o < 32; o <<= 1) {
                sx += __shfl_xor_sync(0xFFFFFFFFu, sx, o);
                sy += __shfl_xor_sync(0xFFFFFFFFu, sy, o);
                qx += __shfl_xor_sync(0xFFFFFFFFu, qx, o);
                qy += __shfl_xor_sync(0xFFFFFFFFu, qy, o);
            }
            if (lane < 4) redAdd4(&stats[gc * 2], sx, qx, sy, qy);
        }
    }
#undef CP_STAGE
#undef COMPUTE
}

// ---------------- batchnorm ----------------------------------------------------
__global__ void bn_finalize(const float* __restrict__ stats,
                            float* __restrict__ mu, float* __restrict__ rsig)
{
    int c = threadIdx.x + blockIdx.x * blockDim.x;
    if (c >= HID) return;
    float m = stats[c * 2] * (1.f / NN);
    float var = stats[c * 2 + 1] * (1.f / NN) - m * m;
    mu[c] = m;
    rsig[c] = rsqrtf(var + 1e-5f);
}

__global__ void bn_apply_sigmoid(__half* __restrict__ X,
                                 const float* __restrict__ mu, const float* __restrict__ rsig,
                                 const float* __restrict__ g, const float* __restrict__ be)
{
    size_t i = (size_t)blockIdx.x * blockDim.x + threadIdx.x;
    if (i >= (size_t)NN * HID / 4) return;
    size_t base = i * 4;
    int c = (int)(base & (HID - 1));
    float4 x = ld4h(X + base);
    float4 y;
    y.x = (x.x - mu[c])     * rsig[c]     * g[c]     + be[c];
    y.y = (x.y - mu[c + 1]) * rsig[c + 1] * g[c + 1] + be[c + 1];
    y.z = (x.z - mu[c + 2]) * rsig[c + 2] * g[c + 2] + be[c + 2];
    y.w = (x.w - mu[c + 3]) * rsig[c + 3] * g[c + 3] + be[c + 3];
    y.x = 1.f / (1.f + expf(-y.x));
    y.y = 1.f / (1.f + expf(-y.y));
    y.z = 1.f / (1.f + expf(-y.z));
    y.w = 1.f / (1.f + expf(-y.w));
    st4h(X + base, y);
}

// ---------------- launch --------------------------------------------------------
extern "C" void kernel_launch(void* const* d_in, const int* in_sizes, int n_in,
                              void* d_out, int out_size)
{
    const float* x_gsage = (const float*)d_in[0];
    const int*   ei      = (const int*)d_in[1];
    const float* x_mlp   = (const float*)d_in[2];
    const float* Wq = (const float*)d_in[3];  const float* bq = (const float*)d_in[4];
    const float* Wk = (const float*)d_in[5];  const float* bk = (const float*)d_in[6];
    const float* Wv = (const float*)d_in[7];  const float* bv = (const float*)d_in[8];
    const float* Ws = (const float*)d_in[9];  const float* bs = (const float*)d_in[10];
    const float* W1 = (const float*)d_in[11];
    const float* g1 = (const float*)d_in[13]; const float* be1 = (const float*)d_in[14];
    const float* W2 = (const float*)d_in[15];
    const float* g2 = (const float*)d_in[17]; const float* be2 = (const float*)d_in[18];
    const float* W3 = (const float*)d_in[19]; const float* b3 = (const float*)d_in[20];
    const float* alpha = (const float*)d_in[21];
    const float* beta  = (const float*)d_in[22];
    const float* Wc1 = (const float*)d_in[23]; const float* bc1 = (const float*)d_in[24];
    const float* Wc2 = (const float*)d_in[25]; const float* bc2 = (const float*)d_in[26];
    float* out = (float*)d_out;

    __half *qkvs, *h1, *h2, *wh, *xg, *xm;
    float *bcat, *stats1, *stats2, *mu1, *rsig1, *mu2, *rsig2;
    cudaGetSymbolAddress((void**)&qkvs, g_qkvs);
    cudaGetSymbolAddress((void**)&h1, g_h1);
    cudaGetSymbolAddress((void**)&h2, g_h2);
    cudaGetSymbolAddress((void**)&wh, g_wh);
    cudaGetSymbolAddress((void**)&xg, g_xg);
    cudaGetSymbolAddress((void**)&xm, g_xm);
    cudaGetSymbolAddress((void**)&bcat, g_bcat);
    cudaGetSymbolAddress((void**)&stats1, g_stats1);
    cudaGetSymbolAddress((void**)&stats2, g_stats2);
    cudaGetSymbolAddress((void**)&mu1, g_mu1);
    cudaGetSymbolAddress((void**)&rsig1, g_rsig1);
    cudaGetSymbolAddress((void**)&mu2, g_mu2);
    cudaGetSymbolAddress((void**)&rsig2, g_rsig2);

    static cudaStream_t s1 = nullptr, s2 = nullptr;
    static cudaEvent_t evStart, evPre, evXg, evCSR, evMLP;
    if (!s1) {
        cudaStreamCreateWithFlags(&s1, cudaStreamNonBlocking);
        cudaStreamCreateWithFlags(&s2, cudaStreamNonBlocking);
        cudaEventCreateWithFlags(&evStart, cudaEventDisableTiming);
        cudaEventCreateWithFlags(&evPre,  cudaEventDisableTiming);
        cudaEventCreateWithFlags(&evXg,   cudaEventDisableTiming);
        cudaEventCreateWithFlags(&evCSR,  cudaEventDisableTiming);
        cudaEventCreateWithFlags(&evMLP,  cudaEventDisableTiming);
        cudaFuncSetAttribute(gemm, cudaFuncAttributeMaxDynamicSharedMemorySize, 61440);
    }

    const int SMB = 61440;             // 3 stages x (A+B) x 10240 B
    const int MB = (NN + 127) / 128;
    const int NXE = NN * 256;          // elems per x matrix
    dim3 blk(256);

    cudaEventRecord(evStart, 0);

    // ---- s1: cvt_xg in parallel with preconv, then CSR build ----
    cudaStreamWaitEvent(s1, evStart, 0);
    cvt_f2h<<<(NXE / 8 + 255) / 256, blk, 0, s1>>>(x_gsage, xg, NXE);
    cudaEventRecord(evXg, s1);
    zero_deg<<<(NN + 255) / 256, blk, 0, s1>>>();
    count_deg<<<(EE + 255) / 256, blk, 0, s1>>>(ei);
    deg_block_sums<<<NBLK, blk, 0, s1>>>();
    scan_bsums<<<1, blk, 0, s1>>>();
    write_offsets<<<NBLK, blk, 0, s1>>>();
    scatter_edges<<<(EE + 255) / 256, blk, 0, s1>>>(ei);
    cudaEventRecord(evCSR, s1);

    // ---- main: preconv + init, then qkvs GEMM (waits on xg) ----
    preconv<<<(WTF_TOT + QS + 255) / 256, blk>>>(Wq, Wk, Wv, Ws, W1, W2, W3, Wc1, Wc2,
                                                 bq, bk, bv, bs);
    init_stats<<<4, blk>>>();
    cudaEventRecord(evPre, 0);
    cudaStreamWaitEvent(0, evXg, 0);
    gemm<<<dim3(8, MB), blk, SMB>>>(xg, 256, wh + OFF_QKVS, bcat, qkvs, QS,
                                    NN, 1024, 256, 0 | 16, nullptr, nullptr, nullptr);

    // ---- fork s2: MLP branch (convert + GEMMs), overlaps GNN ----
    cudaStreamWaitEvent(s2, evPre, 0);
    cvt_f2h<<<(NXE / 8 + 255) / 256, blk, 0, s2>>>(x_mlp, xm, NXE);
    gemm<<<dim3(4, MB), blk, SMB, s2>>>(xm, 256, wh + OFF_W1, nullptr, h1, HID,
                                        NN, HID, 256, 2 | 16, stats1, nullptr, nullptr);
    bn_finalize<<<2, blk, 0, s2>>>(stats1, mu1, rsig1);
    bn_apply_sigmoid<<<((size_t)NN * HID / 4 + 255) / 256, blk, 0, s2>>>(h1, mu1, rsig1, g1, be1);
    gemm<<<dim3(4, MB), blk, SMB, s2>>>(h1, HID, wh + OFF_W2, nullptr, h2, HID,
                                        NN, HID, HID, 2 | 16, stats2, nullptr, nullptr);
    bn_finalize<<<2, blk, 0, s2>>>(stats2, mu2, rsig2);
    bn_apply_sigmoid<<<((size_t)NN * HID / 4 + 255) / 256, blk, 0, s2>>>(h2, mu2, rsig2, g2, be2);
    cudaEventRecord(evMLP, s2);

    // ---- main: attention (needs qkvs + CSR) ----
    cudaStreamWaitEvent(0, evCSR, 0);
    attn_fused<<<(NN + 7) / 8, blk>>>();

    // ---- join: W3 needs h2 (s2) and hg (main) ----
    cudaStreamWaitEvent(0, evMLP, 0);
    gemm<<<dim3(2, MB), blk, SMB>>>(h2, HID, wh + OFF_W3, b3, qkvs + 768, QS,
                                    NN, HC, HID, 3 | 16, nullptr, alpha, beta);

    // classifier
    gemm<<<dim3(4, MB), blk, SMB>>>(qkvs + 768, QS, wh + OFF_WC1, bc1, h1, HID,
                                    NN, HID, HC, 1 | 16, nullptr, nullptr, nullptr);
    gemm<<<dim3(1, MB), blk, SMB>>>(h1, HID, wh + OFF_WC2, bc2, out, NCLS,
                                    NN, NCLS, HID, 0, nullptr, nullptr, nullptr);
}